// round 1
// baseline (speedup 1.0000x reference)
#include <cuda_runtime.h>
#include <cuda_bf16.h>
#include <stdint.h>

// ---------------------------------------------------------------------------
// Chamfer distance, N = M = 16384, D = 3, fp32.
//   d2[i][j] = |a_i|^2 + |b_j|^2 - 2 a_i . b_j   (same form as reference)
//   out = mean_i min_j d2 + mean_j min_i d2
//
// min_j d2 = |a|^2 + 2 * min_j ( 0.5|b_j|^2 - a.b_j )
// Inner loop per pair: 3 FMA + 1 min. Packed f32x2 FFMA processes 2 j's/op.
//
// Work decomposition: 128 point-tiles (256 pts) x 37 segments (~443 pts)
// = 4736 units = 592 CTAs x 8 units = 4 CTAs/SM x 148 SMs, one balanced wave.
// Partial per-(point,segment) mins merged via atomicMin on monotone uint
// encoding of float; finalize kernel decodes, clamps, sums (deterministic).
// ---------------------------------------------------------------------------

typedef unsigned long long ull;

#define NPTS        16384
#define NTILES      128        // 32768 points total / 256
#define NSEG        37
#define TPB         256
#define NCTAS       592        // 128*37 / 8
#define UNITS_PER_CTA 8
#define MAX_NP      224        // max pair-groups per segment (ceil(443/2)=222, padded)

__device__ unsigned int g_min[2 * NPTS];

__device__ __forceinline__ ull ffma2(ull a, ull b, ull c) {
    ull d;
    asm("fma.rn.f32x2 %0, %1, %2, %3;" : "=l"(d) : "l"(a), "l"(b), "l"(c));
    return d;
}
__device__ __forceinline__ ull pack2f(float lo, float hi) {
    ull d;
    asm("mov.b64 %0, {%1, %2};" : "=l"(d) : "f"(lo), "f"(hi));
    return d;
}
__device__ __forceinline__ void unpack2f(ull v, float& lo, float& hi) {
    asm("mov.b64 {%0, %1}, %2;" : "=f"(lo), "=f"(hi) : "l"(v));
}

// monotone bijection float -> uint (preserves <)
__device__ __forceinline__ unsigned int enc_f(float f) {
    unsigned int b = __float_as_uint(f);
    return (b & 0x80000000u) ? ~b : (b | 0x80000000u);
}
__device__ __forceinline__ float dec_f(unsigned int u) {
    unsigned int b = (u & 0x80000000u) ? (u & 0x7FFFFFFFu) : ~u;
    return __uint_as_float(b);
}

__global__ void init_kernel() {
    int i = blockIdx.x * blockDim.x + threadIdx.x;
    if (i < 2 * NPTS) g_min[i] = 0xFFFFFFFFu;  // encodes +max
}

__global__ __launch_bounds__(TPB, 4)
void chamfer_scan(const float* __restrict__ pa, const float* __restrict__ pb) {
    // SMEM per pair-group pg: floats [x0,x1,y0,y1,z0,z1,h0,h1]
    __shared__ __align__(16) float s[MAX_NP * 8];
    const int tid = threadIdx.x;

    for (int k = 0; k < UNITS_PER_CTA; ++k) {
        const int u    = blockIdx.x * UNITS_PER_CTA + k;
        const int tile = u / NSEG;
        const int seg  = u - tile * NSEG;
        const int j_lo = (seg * NPTS) / NSEG;
        const int j_hi = ((seg + 1) * NPTS) / NSEG;
        const int len  = j_hi - j_lo;
        const int np   = (len + 1) >> 1;

        const bool isA = (tile < 64);
        const float* __restrict__ scan = isA ? pb : pa;  // array being scanned
        const float* __restrict__ own  = isA ? pa : pb;  // array owning this tile
        const int pid  = (isA ? tile : tile - 64) * TPB + tid;

        __syncthreads();  // protect smem reads of previous unit before refill
        for (int l = tid; l < np * 2; l += TPB) {
            float x, y, z, h;
            if (l < len) {
                const int j = j_lo + l;
                x = scan[3 * j + 0];
                y = scan[3 * j + 1];
                z = scan[3 * j + 2];
                h = 0.5f * (x * x + y * y + z * z);
            } else {
                x = 0.f; y = 0.f; z = 0.f; h = 1e30f;  // sentinel: never the min
            }
            const int pg = l >> 1, ln = l & 1;
            float* g = s + pg * 8;
            g[0 + ln] = x;
            g[2 + ln] = y;
            g[4 + ln] = z;
            g[6 + ln] = h;
        }
        __syncthreads();

        const float ax = own[3 * pid + 0];
        const float ay = own[3 * pid + 1];
        const float az = own[3 * pid + 2];
        const ull NAX = pack2f(-ax, -ax);
        const ull NAY = pack2f(-ay, -ay);
        const ull NAZ = pack2f(-az, -az);

        float m0 = 3e38f, m1 = 3e38f;
        const ulonglong2* __restrict__ q = (const ulonglong2*)s;

        #pragma unroll 4
        for (int pg = 0; pg < np; ++pg) {
            const ulonglong2 q0 = q[2 * pg + 0];  // (x0,x1) (y0,y1)
            const ulonglong2 q1 = q[2 * pg + 1];  // (z0,z1) (h0,h1)
            ull v = ffma2(q0.x, NAX, q1.y);       // h - ax*bx
            v = ffma2(q0.y, NAY, v);              //   - ay*by
            v = ffma2(q1.x, NAZ, v);              //   - az*bz
            float v0, v1;
            unpack2f(v, v0, v1);
            m0 = fminf(m0, v0);
            m1 = fminf(m1, v1);
        }
        const float m = fminf(m0, m1);
        atomicMin(&g_min[(isA ? 0 : NPTS) + pid], enc_f(m));
    }
}

__global__ void finalize_kernel(const float* __restrict__ pa,
                                const float* __restrict__ pb,
                                float* __restrict__ out) {
    __shared__ float red[1024];
    const int tid = threadIdx.x;
    float acc = 0.0f;
    for (int i = tid; i < 2 * NPTS; i += 1024) {
        const float v = dec_f(g_min[i]);
        const float* src = (i < NPTS) ? (pa + 3 * i) : (pb + 3 * (i - NPTS));
        const float x = src[0], y = src[1], z = src[2];
        const float a2 = x * x + y * y + z * z;
        const float d2 = fmaxf(fmaf(2.0f, v, a2), 0.0f);
        acc += d2;
    }
    red[tid] = acc;
    __syncthreads();
    for (int off = 512; off > 0; off >>= 1) {
        if (tid < off) red[tid] += red[tid + off];
        __syncthreads();
    }
    if (tid == 0) out[0] = red[0] * (1.0f / (float)NPTS);
}

extern "C" void kernel_launch(void* const* d_in, const int* in_sizes, int n_in,
                              void* d_out, int out_size) {
    const float* p_hat = (const float*)d_in[0];  // A, [16384,3]
    const float* p     = (const float*)d_in[1];  // B, [16384,3]
    float* out = (float*)d_out;

    init_kernel<<<(2 * NPTS + 1023) / 1024, 1024>>>();
    chamfer_scan<<<NCTAS, TPB>>>(p_hat, p);
    finalize_kernel<<<1, 1024>>>(p_hat, p, out);
}

// round 2
// speedup vs baseline: 1.4662x; 1.4662x over previous
#include <cuda_runtime.h>
#include <cuda_bf16.h>
#include <stdint.h>

// ---------------------------------------------------------------------------
// Chamfer distance, N = M = 16384, D = 3, fp32.
//   min_j d2(a, b_j) = |a|^2 + 2 * min_j ( 0.5|b_j|^2 - a.b_j )
// Hot loop per pair-group (2 scan pts) x 4 own pts: 2 LDS.128 + 12 FFMA2
// + 8 FMNMX = 22 issue slots / 8 pairs; fma-pipe floor 24 cyc / 256 pairs
// per SMSP => ~44us chip floor.
//
// Decomposition: 32 tiles (1024 own pts, 4/thread) x 37 scan segments
// = 1184 units = 592 CTAs x 2 = 4 CTAs/SM x 148 SMs, one balanced wave.
// Launch 1 (precompute): pack scan data {(x0,x1),(y0,y1)},{(z0,z1),(h0,h1)}
//   + init g_min + reset counter.
// Launch 2 (scan): FFMA2 mainloop, atomicMin merge, last CTA finalizes.
// ---------------------------------------------------------------------------

typedef unsigned long long ull;

#define NPTS   16384
#define NPG    8192          // pair-groups per array
#define NSEG   37
#define TPB    256
#define NTILES 32            // 16 per array, 1024 own points each
#define NUNITS (NTILES * NSEG)   // 1184
#define NCTAS  592               // 1184 / 2
#define MAX_NP 224               // max pair-groups per segment (<=222)

__device__ ulonglong2 g_pk[2][NPG][2];   // [arr][pg][0]={xx,yy} [1]={zz,hh}
__device__ unsigned int g_min[2 * NPTS];
__device__ unsigned int g_ctr;

__device__ __forceinline__ ull ffma2(ull a, ull b, ull c) {
    ull d;
    asm("fma.rn.f32x2 %0, %1, %2, %3;" : "=l"(d) : "l"(a), "l"(b), "l"(c));
    return d;
}
__device__ __forceinline__ ull pack2f(float lo, float hi) {
    ull d;
    asm("mov.b64 %0, {%1, %2};" : "=l"(d) : "f"(lo), "f"(hi));
    return d;
}
__device__ __forceinline__ void unpack2f(ull v, float& lo, float& hi) {
    asm("mov.b64 {%0, %1}, %2;" : "=f"(lo), "=f"(hi) : "l"(v));
}
// monotone bijection float -> uint (preserves <)
__device__ __forceinline__ unsigned int enc_f(float f) {
    unsigned int b = __float_as_uint(f);
    return (b & 0x80000000u) ? ~b : (b | 0x80000000u);
}
__device__ __forceinline__ float dec_f(unsigned int u) {
    unsigned int b = (u & 0x80000000u) ? (u & 0x7FFFFFFFu) : ~u;
    return __uint_as_float(b);
}

// 64 CTAs x 256 = 16384 threads: one thread per (arr, pg); also init g_min/ctr.
__global__ void precompute(const float* __restrict__ pa,
                           const float* __restrict__ pb) {
    const int t = blockIdx.x * blockDim.x + threadIdx.x;   // 0..16383
    const int arr = t >> 13;          // 0 = pa, 1 = pb
    const int pg  = t & (NPG - 1);
    const float2* __restrict__ src =
        (const float2*)(arr ? pb : pa);                    // 8B aligned, 24B/pg
    const float2 f0 = src[3 * pg + 0];   // x0 y0
    const float2 f1 = src[3 * pg + 1];   // z0 x1
    const float2 f2 = src[3 * pg + 2];   // y1 z1
    const float x0 = f0.x, y0 = f0.y, z0 = f1.x;
    const float x1 = f1.y, y1 = f2.x, z1 = f2.y;
    const float h0 = 0.5f * (x0 * x0 + y0 * y0 + z0 * z0);
    const float h1 = 0.5f * (x1 * x1 + y1 * y1 + z1 * z1);
    ulonglong2 u0, u1;
    u0.x = pack2f(x0, x1); u0.y = pack2f(y0, y1);
    u1.x = pack2f(z0, z1); u1.y = pack2f(h0, h1);
    g_pk[arr][pg][0] = u0;
    g_pk[arr][pg][1] = u1;

    g_min[t] = 0xFFFFFFFFu;
    g_min[t + NPTS] = 0xFFFFFFFFu;
    if (t == 0) g_ctr = 0u;
}

__global__ __launch_bounds__(TPB, 4)
void chamfer_scan(const float* __restrict__ pa, const float* __restrict__ pb,
                  float* __restrict__ out) {
    __shared__ __align__(16) ulonglong2 s[2 * MAX_NP];
    __shared__ unsigned int s_last;
    __shared__ float red[TPB];
    const int tid = threadIdx.x;

    for (int u = blockIdx.x; u < NUNITS; u += NCTAS) {
        const int tile = u / NSEG;
        const int seg  = u - tile * NSEG;
        const int j_lo = ((seg * NPTS) / NSEG) & ~1;
        const int j_hi = ((seg + 1) * NPTS) / NSEG;
        const int np   = (j_hi - j_lo + 1) >> 1;
        const int a    = tile >> 4;                 // 0: own=pa scan=pb
        const ulonglong2* __restrict__ pk = &g_pk[1 - a][j_lo >> 1][0];
        const float* __restrict__ own = a ? pb : pa;
        const int pid = (tile & 15) * 1024 + tid;

        __syncthreads();   // protect smem of previous unit
        for (int l = tid; l < 2 * np; l += TPB) s[l] = pk[l];
        __syncthreads();

        ull NX[4], NY[4], NZ[4];
        #pragma unroll
        for (int c = 0; c < 4; ++c) {
            const float ax = own[3 * (pid + 256 * c) + 0];
            const float ay = own[3 * (pid + 256 * c) + 1];
            const float az = own[3 * (pid + 256 * c) + 2];
            NX[c] = pack2f(-ax, -ax);
            NY[c] = pack2f(-ay, -ay);
            NZ[c] = pack2f(-az, -az);
        }

        float m[4][2];
        #pragma unroll
        for (int c = 0; c < 4; ++c) { m[c][0] = 3e38f; m[c][1] = 3e38f; }

        #pragma unroll 2
        for (int pg = 0; pg < np; ++pg) {
            const ulonglong2 q0 = s[2 * pg + 0];   // (x0,x1) (y0,y1)
            const ulonglong2 q1 = s[2 * pg + 1];   // (z0,z1) (h0,h1)
            #pragma unroll
            for (int c = 0; c < 4; ++c) {
                ull v = ffma2(q0.x, NX[c], q1.y);
                v = ffma2(q0.y, NY[c], v);
                v = ffma2(q1.x, NZ[c], v);
                float v0, v1;
                unpack2f(v, v0, v1);
                m[c][0] = fminf(m[c][0], v0);
                m[c][1] = fminf(m[c][1], v1);
            }
        }

        const unsigned int base = a ? (unsigned)NPTS : 0u;
        #pragma unroll
        for (int c = 0; c < 4; ++c)
            atomicMin(&g_min[base + pid + 256 * c],
                      enc_f(fminf(m[c][0], m[c][1])));
    }

    // ---- last-CTA finalize (deterministic fixed-order reduction) ----
    __threadfence();
    if (tid == 0) s_last = (atomicAdd(&g_ctr, 1u) == (unsigned)(NCTAS - 1));
    __syncthreads();
    if (!s_last) return;
    __threadfence();

    float acc = 0.0f;
    for (int i = tid; i < 2 * NPTS; i += TPB) {
        const float v = dec_f(__ldcg(&g_min[i]));
        const float* src = (i < NPTS) ? (pa + 3 * i) : (pb + 3 * (i - NPTS));
        const float x = src[0], y = src[1], z = src[2];
        const float d2 = fmaxf(fmaf(2.0f, v, x * x + y * y + z * z), 0.0f);
        acc += d2;
    }
    red[tid] = acc;
    __syncthreads();
    for (int off = TPB / 2; off > 0; off >>= 1) {
        if (tid < off) red[tid] += red[tid + off];
        __syncthreads();
    }
    if (tid == 0) out[0] = red[0] * (1.0f / (float)NPTS);
}

extern "C" void kernel_launch(void* const* d_in, const int* in_sizes, int n_in,
                              void* d_out, int out_size) {
    const float* p_hat = (const float*)d_in[0];  // [16384,3]
    const float* p     = (const float*)d_in[1];  // [16384,3]
    float* out = (float*)d_out;

    precompute<<<64, 256>>>(p_hat, p);
    chamfer_scan<<<NCTAS, TPB>>>(p_hat, p, out);
}